// round 2
// baseline (speedup 1.0000x reference)
#include <cuda_runtime.h>
#include <math.h>
#include <stdint.h>

// ---------------- problem constants ----------------
#define B_   32
#define S_   197
#define D_   768
#define H_   12
#define DH_  64
#define F_   3072
#define L_   12
#define NP_  14
#define P_   16
#define IMG_ 224
#define NTOK (B_ * S_)          // 6304
#define NPAT (B_ * NP_ * NP_)   // 6272

// ---------------- scratch (device globals; no allocation allowed) ----------------
__device__ float g_x[NTOK * D_];
__device__ float g_h[NTOK * D_];
__device__ float g_q[NTOK * D_];
__device__ float g_k[NTOK * D_];
__device__ float g_v[NTOK * D_];
__device__ float g_attn[NTOK * D_];
__device__ float g_ffh[NTOK * F_];   // also used as im2col scratch at start
__device__ float g_cls[B_ * D_];

// ---------------- im2col for patch embedding ----------------
// out[m, k]: m = b*196 + ph*14 + pw ; k = c*256 + p*16 + q
__global__ void im2col_kernel(const float* __restrict__ X, float* __restrict__ out) {
    int idx = blockIdx.x * 256 + threadIdx.x;          // < 6272*768 exactly
    int k = idx % 768;
    int m = idx / 768;
    int c = k >> 8;            // /256
    int pq = k & 255;
    int p = pq >> 4, q = pq & 15;
    int b = m / 196;
    int hw = m - b * 196;
    int ph = hw / 14, pw = hw - ph * 14;
    out[idx] = X[(((size_t)(b * 3 + c) * IMG_) + ph * 16 + p) * IMG_ + pw * 16 + q];
}

// ---------------- pos-emb add + cls token ----------------
__global__ void posadd_kernel(float* __restrict__ x, const float* __restrict__ cls,
                              const float* __restrict__ pos) {
    int idx = blockIdx.x * 256 + threadIdx.x;          // < 32*197*768 exactly
    int d = idx % D_;
    int s = (idx / D_) % S_;
    if (s == 0) x[idx] = cls[d] + pos[d];
    else        x[idx] += pos[s * D_ + d];
}

// ---------------- LayerNorm (block per row, 256 threads, D=768) ----------------
__global__ void ln_kernel(const float* __restrict__ x, const float* __restrict__ g,
                          const float* __restrict__ bb, float* __restrict__ y, int rowMul) {
    const int row = blockIdx.x * rowMul;
    const float* xr = x + (size_t)row * D_;
    float* yr = y + (size_t)blockIdx.x * D_;
    const int tid = threadIdx.x;
    float v0 = xr[tid], v1 = xr[tid + 256], v2 = xr[tid + 512];
    float s = v0 + v1 + v2;
    float q = v0 * v0 + v1 * v1 + v2 * v2;
    __shared__ float sh[18];
    int lane = tid & 31, wid = tid >> 5;
#pragma unroll
    for (int off = 16; off > 0; off >>= 1) {
        s += __shfl_down_sync(0xffffffffu, s, off);
        q += __shfl_down_sync(0xffffffffu, q, off);
    }
    if (lane == 0) { sh[wid] = s; sh[8 + wid] = q; }
    __syncthreads();
    if (tid == 0) {
        float S = 0.f, Q = 0.f;
#pragma unroll
        for (int i = 0; i < 8; i++) { S += sh[i]; Q += sh[8 + i]; }
        float mean = S * (1.0f / D_);
        float var = Q * (1.0f / D_) - mean * mean;
        sh[16] = mean;
        sh[17] = rsqrtf(var + 1e-5f);
    }
    __syncthreads();
    float mean = sh[16], rstd = sh[17];
    yr[tid]       = (v0 - mean) * rstd * g[tid]       + bb[tid];
    yr[tid + 256] = (v1 - mean) * rstd * g[tid + 256] + bb[tid + 256];
    yr[tid + 512] = (v2 - mean) * rstd * g[tid + 512] + bb[tid + 512];
}

// ---------------- SGEMM 128x128x8, 256 threads, double-buffered ----------------
// C[m,n] = sum_k A[m,k] * B[k,n]           (BT=false)
// C[m,n] = sum_k A[m,k] * B[n,k]           (BT=true)
// EPI: 0 = +bias ; 1 = +bias+Res ; 2 = gelu(+bias) ; 3 = qkv head scatter ; 4 = patch scatter
// Assumes N % 128 == 0 and K % 8 == 0 (true for all call sites). M guarded.
template <bool BT, int EPI>
__global__ __launch_bounds__(256)
void sgemm_kernel(const float* __restrict__ A, const float* __restrict__ Bm,
                  const float* __restrict__ bias, const float* __restrict__ Res,
                  float* __restrict__ C, int M, int N, int K) {
    __shared__ __align__(16) float As[2][8][128];
    __shared__ __align__(16) float Bs[2][8][128];
    const int tid = threadIdx.x;
    const int nBase = blockIdx.x * 128;
    const int mBase = blockIdx.y * 128;
    const int tx = tid & 15, ty = tid >> 4;
    const int arow = tid >> 1;
    const int acol = (tid & 1) * 4;
    const int brow = tid >> 5;
    const int bcol = (tid & 31) * 4;
    const bool aval = (mBase + arow) < M;

    float acc[8][8];
#pragma unroll
    for (int i = 0; i < 8; i++)
#pragma unroll
        for (int j = 0; j < 8; j++) acc[i][j] = 0.f;

    const int KT = K >> 3;
    float4 av, bv;

    // prologue: tile 0
    av = aval ? *(const float4*)(A + (size_t)(mBase + arow) * K + acol)
              : make_float4(0.f, 0.f, 0.f, 0.f);
    if (BT) bv = *(const float4*)(Bm + (size_t)(nBase + arow) * K + acol);
    else    bv = *(const float4*)(Bm + (size_t)brow * N + nBase + bcol);
    As[0][acol + 0][arow] = av.x; As[0][acol + 1][arow] = av.y;
    As[0][acol + 2][arow] = av.z; As[0][acol + 3][arow] = av.w;
    if (BT) {
        Bs[0][acol + 0][arow] = bv.x; Bs[0][acol + 1][arow] = bv.y;
        Bs[0][acol + 2][arow] = bv.z; Bs[0][acol + 3][arow] = bv.w;
    } else {
        *(float4*)&Bs[0][brow][bcol] = bv;
    }
    __syncthreads();

    int buf = 0;
    for (int kt = 0; kt < KT; ++kt) {
        const bool hn = (kt + 1) < KT;
        if (hn) {
            int k0 = (kt + 1) << 3;
            av = aval ? *(const float4*)(A + (size_t)(mBase + arow) * K + k0 + acol)
                      : make_float4(0.f, 0.f, 0.f, 0.f);
            if (BT) bv = *(const float4*)(Bm + (size_t)(nBase + arow) * K + k0 + acol);
            else    bv = *(const float4*)(Bm + (size_t)(k0 + brow) * N + nBase + bcol);
        }
#pragma unroll
        for (int kk = 0; kk < 8; ++kk) {
            float a[8], b[8];
            *(float4*)&a[0] = *(const float4*)&As[buf][kk][ty * 8];
            *(float4*)&a[4] = *(const float4*)&As[buf][kk][ty * 8 + 4];
            *(float4*)&b[0] = *(const float4*)&Bs[buf][kk][tx * 8];
            *(float4*)&b[4] = *(const float4*)&Bs[buf][kk][tx * 8 + 4];
#pragma unroll
            for (int i = 0; i < 8; i++)
#pragma unroll
                for (int j = 0; j < 8; j++)
                    acc[i][j] = fmaf(a[i], b[j], acc[i][j]);
        }
        if (hn) {
            int nb = buf ^ 1;
            As[nb][acol + 0][arow] = av.x; As[nb][acol + 1][arow] = av.y;
            As[nb][acol + 2][arow] = av.z; As[nb][acol + 3][arow] = av.w;
            if (BT) {
                Bs[nb][acol + 0][arow] = bv.x; Bs[nb][acol + 1][arow] = bv.y;
                Bs[nb][acol + 2][arow] = bv.z; Bs[nb][acol + 3][arow] = bv.w;
            } else {
                *(float4*)&Bs[nb][brow][bcol] = bv;
            }
            __syncthreads();
            buf = nb;
        }
    }

    // epilogue
#pragma unroll
    for (int i = 0; i < 8; i++) {
        int m = mBase + ty * 8 + i;
        if (m >= M) break;
#pragma unroll
        for (int j = 0; j < 8; j++) {
            int n = nBase + tx * 8 + j;
            float v = acc[i][j] + bias[n];
            if (EPI == 0) {
                C[(size_t)m * N + n] = v;
            } else if (EPI == 1) {
                C[(size_t)m * N + n] = v + Res[(size_t)m * N + n];
            } else if (EPI == 2) {
                C[(size_t)m * N + n] = 0.5f * v * (1.0f + erff(v * 0.70710678118654752f));
            } else if (EPI == 3) {
                int b = m / S_, s = m - b * S_;
                int h = n >> 6, dh = n & 63;
                C[(((size_t)(b * H_ + h)) * S_ + s) * DH_ + dh] = v;
            } else { // EPI == 4: patch scatter into token grid (row 1+sp of each batch)
                int b = m / 196, sp = m - b * 196;
                C[((size_t)(b * S_ + 1 + sp)) * D_ + n] = v;
            }
        }
    }
}

// ---------------- attention: block per (b, h) ----------------
// dynamic smem: Kt[64][200] (transposed, padded) + Vs[197][64]
__global__ __launch_bounds__(128)
void attn_kernel(const float* __restrict__ Q, const float* __restrict__ Kg,
                 const float* __restrict__ Vg, float* __restrict__ O) {
    extern __shared__ float sm[];
    float* Kt = sm;                 // 64*200
    float* Vs = sm + 64 * 200;      // 197*64
    __shared__ __align__(16) float qs[4][64];
    __shared__ float probs[4][200];
    const int h = blockIdx.x, b = blockIdx.y;
    const int tid = threadIdx.x, w = tid >> 5, lane = tid & 31;
    const size_t base = ((size_t)(b * H_ + h)) * S_ * DH_;
    const float* Kb = Kg + base;
    const float* Vb = Vg + base;
    const float* Qb = Q + base;

    for (int i = tid; i < S_ * DH_; i += 128) {
        int t = i >> 6, d = i & 63;
        Kt[d * 200 + t] = Kb[i];
    }
    for (int i = tid; i < (S_ * DH_) / 4; i += 128)
        ((float4*)Vs)[i] = ((const float4*)Vb)[i];
    __syncthreads();

    for (int s = w; s < S_; s += 4) {
        if (lane < 16) ((float4*)qs[w])[lane] = ((const float4*)(Qb + (size_t)s * DH_))[lane];
        __syncwarp();
        float lmax = -1e30f;
        for (int t = lane; t < S_; t += 32) {
            float acc = 0.f;
#pragma unroll
            for (int d = 0; d < 64; ++d)
                acc = fmaf(qs[w][d], Kt[d * 200 + t], acc);
            acc *= 0.125f;   // 1/sqrt(64)
            probs[w][t] = acc;
            lmax = fmaxf(lmax, acc);
        }
#pragma unroll
        for (int off = 16; off > 0; off >>= 1)
            lmax = fmaxf(lmax, __shfl_xor_sync(0xffffffffu, lmax, off));
        float lsum = 0.f;
        for (int t = lane; t < S_; t += 32) {
            float p = __expf(probs[w][t] - lmax);
            probs[w][t] = p;
            lsum += p;
        }
#pragma unroll
        for (int off = 16; off > 0; off >>= 1)
            lsum += __shfl_xor_sync(0xffffffffu, lsum, off);
        const float inv = 1.f / lsum;
        __syncwarp();
        float o0 = 0.f, o1 = 0.f;
        for (int t = 0; t < S_; ++t) {
            float p = probs[w][t];
            o0 = fmaf(p, Vs[t * 64 + lane], o0);
            o1 = fmaf(p, Vs[t * 64 + lane + 32], o1);
        }
        float* Or = O + ((size_t)(b * S_ + s)) * D_ + h * DH_;
        Or[lane] = o0 * inv;
        Or[lane + 32] = o1 * inv;
        __syncwarp();
    }
}

// ---------------- classifier head: out[b,n] = cls_ln[b] . head_w[:,n] + head_b[n] ----------------
__global__ void head_kernel(const float* __restrict__ cls, const float* __restrict__ W,
                            const float* __restrict__ bias, float* __restrict__ out) {
    int n = blockIdx.x * 256 + threadIdx.x;
    int b = blockIdx.y;
    if (n >= 1000) return;
    const float* xr = cls + (size_t)b * D_;
    float acc = bias[n];
    for (int k = 0; k < D_; ++k)
        acc = fmaf(xr[k], W[(size_t)k * 1000 + n], acc);
    out[(size_t)b * 1000 + n] = acc;
}

// ---------------- host launch ----------------
extern "C" void kernel_launch(void* const* d_in, const int* in_sizes, int n_in,
                              void* d_out, int out_size) {
    (void)in_sizes; (void)n_in; (void)out_size;
    const float* X        = (const float*)d_in[0];
    const float* patch_w  = (const float*)d_in[1];
    const float* patch_b  = (const float*)d_in[2];
    const float* cls_tok  = (const float*)d_in[3];
    const float* pos_emb  = (const float*)d_in[4];
    const float* ln1_g    = (const float*)d_in[5];
    const float* ln1_b    = (const float*)d_in[6];
    const float* Wq       = (const float*)d_in[7];
    const float* bq       = (const float*)d_in[8];
    const float* Wk       = (const float*)d_in[9];
    const float* bk       = (const float*)d_in[10];
    const float* Wv       = (const float*)d_in[11];
    const float* bv       = (const float*)d_in[12];
    const float* Wo       = (const float*)d_in[13];
    const float* bo       = (const float*)d_in[14];
    const float* ln2_g    = (const float*)d_in[15];
    const float* ln2_b    = (const float*)d_in[16];
    const float* Wf1      = (const float*)d_in[17];
    const float* bf1      = (const float*)d_in[18];
    const float* Wf2      = (const float*)d_in[19];
    const float* bf2      = (const float*)d_in[20];
    const float* lnf_g    = (const float*)d_in[21];
    const float* lnf_b    = (const float*)d_in[22];
    const float* head_w   = (const float*)d_in[23];
    const float* head_b   = (const float*)d_in[24];
    float* out = (float*)d_out;

    float *gx, *gh, *gq, *gk, *gv, *gattn, *gffh, *gcls;
    cudaGetSymbolAddress((void**)&gx, g_x);
    cudaGetSymbolAddress((void**)&gh, g_h);
    cudaGetSymbolAddress((void**)&gq, g_q);
    cudaGetSymbolAddress((void**)&gk, g_k);
    cudaGetSymbolAddress((void**)&gv, g_v);
    cudaGetSymbolAddress((void**)&gattn, g_attn);
    cudaGetSymbolAddress((void**)&gffh, g_ffh);
    cudaGetSymbolAddress((void**)&gcls, g_cls);

    const int ATTN_SMEM = (64 * 200 + S_ * DH_) * 4;   // 101632 bytes
    cudaFuncSetAttribute(attn_kernel, cudaFuncAttributeMaxDynamicSharedMemorySize, ATTN_SMEM);

    // patch embed: im2col (into g_ffh scratch) + GEMM (B transposed) scattering into token grid
    im2col_kernel<<<(NPAT * D_) / 256, 256>>>(X, gffh);
    sgemm_kernel<true, 4><<<dim3(6, 49), 256>>>(gffh, patch_w, patch_b, nullptr, gx,
                                                NPAT, D_, D_);
    posadd_kernel<<<(NTOK * D_) / 256, 256>>>(gx, cls_tok, pos_emb);

    for (int l = 0; l < L_; ++l) {
        const float* wq = Wq + (size_t)l * D_ * D_;
        const float* wk = Wk + (size_t)l * D_ * D_;
        const float* wv = Wv + (size_t)l * D_ * D_;
        const float* wo = Wo + (size_t)l * D_ * D_;
        const float* w1 = Wf1 + (size_t)l * D_ * F_;
        const float* w2 = Wf2 + (size_t)l * F_ * D_;

        ln_kernel<<<NTOK, 256>>>(gx, ln1_g + l * D_, ln1_b + l * D_, gh, 1);
        sgemm_kernel<false, 3><<<dim3(6, 50), 256>>>(gh, wq, bq + l * D_, nullptr, gq, NTOK, D_, D_);
        sgemm_kernel<false, 3><<<dim3(6, 50), 256>>>(gh, wk, bk + l * D_, nullptr, gk, NTOK, D_, D_);
        sgemm_kernel<false, 3><<<dim3(6, 50), 256>>>(gh, wv, bv + l * D_, nullptr, gv, NTOK, D_, D_);
        attn_kernel<<<dim3(H_, B_), 128, ATTN_SMEM>>>(gq, gk, gv, gattn);
        sgemm_kernel<false, 1><<<dim3(6, 50), 256>>>(gattn, wo, bo + l * D_, gx, gx, NTOK, D_, D_);
        ln_kernel<<<NTOK, 256>>>(gx, ln2_g + l * D_, ln2_b + l * D_, gh, 1);
        sgemm_kernel<false, 2><<<dim3(24, 50), 256>>>(gh, w1, bf1 + l * F_, nullptr, gffh, NTOK, F_, D_);
        sgemm_kernel<false, 1><<<dim3(6, 50), 256>>>(gffh, w2, bf2 + l * D_, gx, gx, NTOK, D_, F_);
    }

    // final LN on cls rows only, then head
    ln_kernel<<<B_, 256>>>(gx, lnf_g, lnf_b, gcls, S_);
    head_kernel<<<dim3(4, B_), 256>>>(gcls, head_w, head_b, out);
}

// round 13
// speedup vs baseline: 1.8395x; 1.8395x over previous
#include <cuda_runtime.h>
#include <cuda_bf16.h>
#include <math.h>
#include <stdint.h>

// ---------------- problem constants ----------------
#define B_   32
#define S_   197
#define D_   768
#define H_   12
#define DH_  64
#define F_   3072
#define L_   12
#define NTOK (B_ * S_)          // 6304
#define NPAT (B_ * 196)         // 6272
#define RPAD 6400               // 50 * 128 (padded token rows for MMA tiles)

// weight storage: bf16 hi/lo, transposed to [N][K] (K-major)
#define WSZ      (D_ * D_)                    // 589824
#define LSTRIDE  (4 * WSZ + 2 * D_ * F_)      // 7077888
#define PATCH_OFF (12 * LSTRIDE)
#define WTOT     (PATCH_OFF + WSZ)

// ---------------- scratch (device globals) ----------------
__device__ __nv_bfloat16 g_w_hi[WTOT];
__device__ __nv_bfloat16 g_w_lo[WTOT];
__device__ float g_x[RPAD * D_];
__device__ float g_q[NTOK * D_], g_k[NTOK * D_], g_v[NTOK * D_];
__device__ __nv_bfloat16 g_h_hi[RPAD * D_], g_h_lo[RPAD * D_];
__device__ __nv_bfloat16 g_a_hi[RPAD * D_], g_a_lo[RPAD * D_];
__device__ __nv_bfloat16 g_f_hi[(size_t)RPAD * F_], g_f_lo[(size_t)RPAD * F_];
__device__ float g_cls[B_ * D_];

// ---------------- helpers ----------------
__device__ __forceinline__ uint32_t smem_u32(const void* p) {
    uint32_t a;
    asm("{ .reg .u64 t; cvta.to.shared.u64 t, %1; cvt.u32.u64 %0, t; }" : "=r"(a) : "l"(p));
    return a;
}
__device__ __forceinline__ void split2(float v, __nv_bfloat16& h, __nv_bfloat16& l) {
    h = __float2bfloat16(v);
    l = __float2bfloat16(v - __bfloat162float(h));
}
__device__ __forceinline__ void cpa16(uint32_t dst, const void* src) {
    asm volatile("cp.async.cg.shared.global [%0], [%1], 16;" :: "r"(dst), "l"(src));
}
#define CP_COMMIT() asm volatile("cp.async.commit_group;" ::: "memory")
#define CP_WAIT1()  asm volatile("cp.async.wait_group 1;" ::: "memory")
#define CP_WAIT0()  asm volatile("cp.async.wait_group 0;" ::: "memory")

__device__ __forceinline__ void ldsm4(uint32_t* r, uint32_t addr) {
    asm volatile("ldmatrix.sync.aligned.m8n8.x4.shared.b16 {%0,%1,%2,%3}, [%4];"
                 : "=r"(r[0]), "=r"(r[1]), "=r"(r[2]), "=r"(r[3]) : "r"(addr));
}
__device__ __forceinline__ void ldsm2(uint32_t* r, uint32_t addr) {
    asm volatile("ldmatrix.sync.aligned.m8n8.x2.shared.b16 {%0,%1}, [%2];"
                 : "=r"(r[0]), "=r"(r[1]) : "r"(addr));
}
__device__ __forceinline__ void mma16816(float* c, const uint32_t* a, const uint32_t* b) {
    asm volatile("mma.sync.aligned.m16n8k16.row.col.f32.bf16.bf16.f32 "
                 "{%0,%1,%2,%3}, {%4,%5,%6,%7}, {%8,%9}, {%0,%1,%2,%3};"
                 : "+f"(c[0]), "+f"(c[1]), "+f"(c[2]), "+f"(c[3])
                 : "r"(a[0]), "r"(a[1]), "r"(a[2]), "r"(a[3]), "r"(b[0]), "r"(b[1]));
}

// ---------------- weight split + transpose: W[K][N] fp32 -> WT[N][K] bf16 hi/lo ----------------
__global__ void wsplitT_kernel(const float* __restrict__ src, __nv_bfloat16* __restrict__ dhi,
                               __nv_bfloat16* __restrict__ dlo, int K, int N,
                               size_t srcStride, size_t dstStride) {
    __shared__ float t[32][33];
    const float* Sp = src + blockIdx.z * srcStride;
    __nv_bfloat16* Hi = dhi + blockIdx.z * dstStride;
    __nv_bfloat16* Lo = dlo + blockIdx.z * dstStride;
    int nb = blockIdx.x * 32, kb = blockIdx.y * 32;
    int tx = threadIdx.x, ty = threadIdx.y;
#pragma unroll
    for (int j = 0; j < 32; j += 8)
        t[ty + j][tx] = Sp[(size_t)(kb + ty + j) * N + nb + tx];
    __syncthreads();
#pragma unroll
    for (int j = 0; j < 32; j += 8) {
        float v = t[tx][ty + j];
        __nv_bfloat16 h, l; split2(v, h, l);
        size_t o = (size_t)(nb + ty + j) * K + kb + tx;
        Hi[o] = h; Lo[o] = l;
    }
}

// patch_w is already [N=768][K=768]: elementwise split
__global__ void wsplit_kernel(const float* __restrict__ src, __nv_bfloat16* __restrict__ dhi,
                              __nv_bfloat16* __restrict__ dlo, int n) {
    int i = blockIdx.x * 256 + threadIdx.x;
    if (i >= n) return;
    __nv_bfloat16 h, l; split2(src[i], h, l);
    dhi[i] = h; dlo[i] = l;
}

// ---------------- im2col (bf16 hi/lo out) ----------------
__global__ void im2col_kernel(const float* __restrict__ X, __nv_bfloat16* __restrict__ ohi,
                              __nv_bfloat16* __restrict__ olo) {
    int idx = blockIdx.x * 256 + threadIdx.x;      // < 6272*768 exactly
    int k = idx % 768;
    int m = idx / 768;
    int c = k >> 8;
    int pq = k & 255;
    int p = pq >> 4, q = pq & 15;
    int b = m / 196;
    int hw = m - b * 196;
    int ph = hw / 14, pw = hw - ph * 14;
    float v = X[(((size_t)(b * 3 + c) * 224) + ph * 16 + p) * 224 + pw * 16 + q];
    __nv_bfloat16 h, l; split2(v, h, l);
    ohi[idx] = h; olo[idx] = l;
}

// ---------------- pos-emb add + cls token ----------------
__global__ void posadd_kernel(float* __restrict__ x, const float* __restrict__ cls,
                              const float* __restrict__ pos) {
    int idx = blockIdx.x * 256 + threadIdx.x;
    int d = idx % D_;
    int s = (idx / D_) % S_;
    if (s == 0) x[idx] = cls[d] + pos[d];
    else        x[idx] += pos[s * D_ + d];
}

// ---------------- LayerNorm -> bf16 hi/lo ----------------
__global__ void ln_bf16_kernel(const float* __restrict__ x, const float* __restrict__ g,
                               const float* __restrict__ bb, __nv_bfloat16* __restrict__ yhi,
                               __nv_bfloat16* __restrict__ ylo) {
    const float* xr = x + (size_t)blockIdx.x * D_;
    const int tid = threadIdx.x;
    float v0 = xr[tid], v1 = xr[tid + 256], v2 = xr[tid + 512];
    float s = v0 + v1 + v2, q = v0 * v0 + v1 * v1 + v2 * v2;
    __shared__ float sh[18];
    int lane = tid & 31, wid = tid >> 5;
#pragma unroll
    for (int off = 16; off > 0; off >>= 1) {
        s += __shfl_down_sync(0xffffffffu, s, off);
        q += __shfl_down_sync(0xffffffffu, q, off);
    }
    if (lane == 0) { sh[wid] = s; sh[8 + wid] = q; }
    __syncthreads();
    if (tid == 0) {
        float S = 0.f, Q = 0.f;
#pragma unroll
        for (int i = 0; i < 8; i++) { S += sh[i]; Q += sh[8 + i]; }
        float mean = S * (1.0f / D_);
        sh[16] = mean;
        sh[17] = rsqrtf(Q * (1.0f / D_) - mean * mean + 1e-5f);
    }
    __syncthreads();
    float mean = sh[16], rstd = sh[17];
    size_t base = (size_t)blockIdx.x * D_;
#pragma unroll
    for (int c = 0; c < 3; c++) {
        int d = tid + c * 256;
        float y = (((c == 0) ? v0 : (c == 1) ? v1 : v2) - mean) * rstd * g[d] + bb[d];
        __nv_bfloat16 h, l; split2(y, h, l);
        yhi[base + d] = h; ylo[base + d] = l;
    }
}

// ---------------- LayerNorm fp32 (final, cls rows) ----------------
__global__ void ln_f32_kernel(const float* __restrict__ x, const float* __restrict__ g,
                              const float* __restrict__ bb, float* __restrict__ y, int rowMul) {
    const float* xr = x + (size_t)blockIdx.x * rowMul * D_;
    float* yr = y + (size_t)blockIdx.x * D_;
    const int tid = threadIdx.x;
    float v0 = xr[tid], v1 = xr[tid + 256], v2 = xr[tid + 512];
    float s = v0 + v1 + v2, q = v0 * v0 + v1 * v1 + v2 * v2;
    __shared__ float sh[18];
    int lane = tid & 31, wid = tid >> 5;
#pragma unroll
    for (int off = 16; off > 0; off >>= 1) {
        s += __shfl_down_sync(0xffffffffu, s, off);
        q += __shfl_down_sync(0xffffffffu, q, off);
    }
    if (lane == 0) { sh[wid] = s; sh[8 + wid] = q; }
    __syncthreads();
    if (tid == 0) {
        float S = 0.f, Q = 0.f;
#pragma unroll
        for (int i = 0; i < 8; i++) { S += sh[i]; Q += sh[8 + i]; }
        float mean = S * (1.0f / D_);
        sh[16] = mean;
        sh[17] = rsqrtf(Q * (1.0f / D_) - mean * mean + 1e-5f);
    }
    __syncthreads();
    float mean = sh[16], rstd = sh[17];
    yr[tid]       = (v0 - mean) * rstd * g[tid]       + bb[tid];
    yr[tid + 256] = (v1 - mean) * rstd * g[tid + 256] + bb[tid + 256];
    yr[tid + 512] = (v2 - mean) * rstd * g[tid + 512] + bb[tid + 512];
}

// ---------------- mma.sync bf16x3 GEMM: C[M,N] = A[M,K] * BT[N,K]^T ----------------
// CTA tile 128x128, BK=32, 256 threads (8 warps, 2x4), warp tile 64x32.
// smem per stage: A hi/lo + B hi/lo, each 128 rows x 32 bf16, row stride 80B.
// EPI: 1 = fp32 +bias+Res ; 2 = gelu(+bias) -> bf16 hi/lo ; 3 = qkv scatter ; 4 = patch scatter
#define TSZ   10240u           // one 128x32 tile (stride 80)
#define STG   40960u           // per-stage: Ahi, Alo, Bhi, Blo
#define SMDYN 81920

template <int EPI>
__global__ __launch_bounds__(256)
void mma_gemm(const __nv_bfloat16* __restrict__ Ahi, const __nv_bfloat16* __restrict__ Alo,
              const __nv_bfloat16* __restrict__ Bhi, const __nv_bfloat16* __restrict__ Blo,
              const float* __restrict__ bias, const float* __restrict__ bias2,
              const float* __restrict__ bias3, const float* __restrict__ Res,
              float* __restrict__ Cf, float* __restrict__ Cf2, float* __restrict__ Cf3,
              __nv_bfloat16* __restrict__ Chi, __nv_bfloat16* __restrict__ Clo,
              int M, int N, int K) {
    extern __shared__ __align__(128) char sm[];
    const uint32_t smb = smem_u32(sm);
    const int tid = threadIdx.x, wid = tid >> 5, lane = tid & 31;
    const int mBase = blockIdx.y * 128;
    const int nBase = blockIdx.x * 128;
    const int wm = (wid & 1) * 64;
    const int wn = (wid >> 1) * 32;

    // per-thread load mapping: 2 chunks per tile, chunk c: row=c>>2, cc=c&3
    const int r0 = tid >> 2, cc0 = tid & 3;
    const int r1 = (tid + 256) >> 2, cc1 = tid & 3;   // +256 keeps cc identical
    const uint32_t so0 = (uint32_t)(r0 * 80 + cc0 * 16);
    const uint32_t so1 = (uint32_t)(r1 * 80 + cc1 * 16);

    float acc[4][4][4];
#pragma unroll
    for (int i = 0; i < 4; i++)
#pragma unroll
        for (int j = 0; j < 4; j++)
#pragma unroll
            for (int k = 0; k < 4; k++) acc[i][j][k] = 0.f;

    const int KS = K >> 5;

    // ---- stage loader ----
    auto load_stage = [&](int buf, int k0) {
        const uint32_t sA = smb + buf * STG;
        const uint32_t sB = sA + 2 * TSZ;
        const __nv_bfloat16* a0 = Ahi + (size_t)(mBase + r0) * K + k0 + cc0 * 8;
        const __nv_bfloat16* a1 = Ahi + (size_t)(mBase + r1) * K + k0 + cc1 * 8;
        const __nv_bfloat16* b0 = Bhi + (size_t)(nBase + r0) * K + k0 + cc0 * 8;
        const __nv_bfloat16* b1 = Bhi + (size_t)(nBase + r1) * K + k0 + cc1 * 8;
        const size_t dAl = Alo - Ahi, dBl = Blo - Bhi;
        cpa16(sA + so0, a0);              cpa16(sA + so1, a1);
        cpa16(sA + TSZ + so0, a0 + dAl);  cpa16(sA + TSZ + so1, a1 + dAl);
        cpa16(sB + so0, b0);              cpa16(sB + so1, b1);
        cpa16(sB + TSZ + so0, b0 + dBl);  cpa16(sB + TSZ + so1, b1 + dBl);
    };

    load_stage(0, 0);
    CP_COMMIT();

    for (int kt = 0; kt < KS; ++kt) {
        const int buf = kt & 1;
        if (kt + 1 < KS) {
            load_stage(buf ^ 1, (kt + 1) << 5);
            CP_COMMIT();
            CP_WAIT1();
        } else {
            CP_WAIT0();
        }
        __syncthreads();

        const uint32_t aBase = smb + buf * STG;
        const uint32_t bBase = aBase + 2 * TSZ;
#pragma unroll
        for (int kk = 0; kk < 2; ++kk) {
            uint32_t aH[4][4], aL[4][4];
            const uint32_t aoff = (uint32_t)(kk * 32 + ((lane >> 4) & 1) * 16);
#pragma unroll
            for (int mi = 0; mi < 4; ++mi) {
                uint32_t ad = aBase + (uint32_t)((wm + mi * 16 + (lane & 15)) * 80) + aoff;
                ldsm4(aH[mi], ad);
                ldsm4(aL[mi], ad + TSZ);
            }
            const uint32_t boff = (uint32_t)(kk * 32 + ((lane >> 3) & 1) * 16);
#pragma unroll
            for (int ni = 0; ni < 4; ++ni) {
                uint32_t bd = bBase + (uint32_t)((wn + ni * 8 + (lane & 7)) * 80) + boff;
                uint32_t bh[2], bl[2];
                ldsm2(bh, bd);
                ldsm2(bl, bd + TSZ);
#pragma unroll
                for (int mi = 0; mi < 4; ++mi) {
                    mma16816(acc[mi][ni], aH[mi], bh);
                    mma16816(acc[mi][ni], aH[mi], bl);
                    mma16816(acc[mi][ni], aL[mi], bh);
                }
            }
        }
        __syncthreads();
    }

    // ---- epilogue ----
    const int mrow = mBase + wm + (lane >> 2);
    const int ncol0 = nBase + wn + (lane & 3) * 2;
#pragma unroll
    for (int mi = 0; mi < 4; ++mi) {
#pragma unroll
        for (int half = 0; half < 2; ++half) {
            const int m = mrow + mi * 16 + half * 8;
            if (m >= M) continue;
#pragma unroll
            for (int ni = 0; ni < 4; ++ni) {
                const int n = ncol0 + ni * 8;
#pragma unroll
                for (int j = 0; j < 2; ++j) {
                    const int nn = n + j;
                    float v = acc[mi][ni][half * 2 + j];
                    if (EPI == 1) {
                        v += bias[nn];
                        Cf[(size_t)m * N + nn] = v + Res[(size_t)m * N + nn];
                    } else if (EPI == 2) {
                        v += bias[nn];
                        float gg = 0.5f * v * (1.0f + erff(v * 0.70710678118654752f));
                        __nv_bfloat16 h, l; split2(gg, h, l);
                        Chi[(size_t)m * N + nn] = h;
                        Clo[(size_t)m * N + nn] = l;
                    } else if (EPI == 3) {
                        int which = (nn < 768) ? 0 : (nn < 1536) ? 1 : 2;
                        int nq = nn - which * 768;
                        v += (which == 0) ? bias[nq] : (which == 1) ? bias2[nq] : bias3[nq];
                        float* dst = (which == 0) ? Cf : (which == 1) ? Cf2 : Cf3;
                        int b = m / S_, ss = m - b * S_;
                        int h = nq >> 6, dh = nq & 63;
                        dst[(((size_t)(b * H_ + h)) * S_ + ss) * DH_ + dh] = v;
                    } else { // EPI == 4
                        v += bias[nn];
                        int b = m / 196, sp = m - b * 196;
                        Cf[((size_t)(b * S_ + 1 + sp)) * D_ + nn] = v;
                    }
                }
            }
        }
    }
}

// ---------------- attention: block per (b, h), fp32, bf16 hi/lo output ----------------
__global__ __launch_bounds__(128)
void attn_kernel(const float* __restrict__ Q, const float* __restrict__ Kg,
                 const float* __restrict__ Vg, __nv_bfloat16* __restrict__ Ohi,
                 __nv_bfloat16* __restrict__ Olo) {
    extern __shared__ float smf[];
    float* Kt = smf;                 // 64*200
    float* Vs = smf + 64 * 200;      // 197*64
    __shared__ __align__(16) float qs[4][64];
    __shared__ float probs[4][200];
    const int h = blockIdx.x, b = blockIdx.y;
    const int tid = threadIdx.x, w = tid >> 5, lane = tid & 31;
    const size_t base = ((size_t)(b * H_ + h)) * S_ * DH_;
    const float* Kb = Kg + base;
    const float* Vb = Vg + base;
    const float* Qb = Q + base;

    for (int i = tid; i < S_ * DH_; i += 128) {
        int t = i >> 6, d = i & 63;
        Kt[d * 200 + t] = Kb[i];
    }
    for (int i = tid; i < (S_ * DH_) / 4; i += 128)
        ((float4*)Vs)[i] = ((const float4*)Vb)[i];
    __syncthreads();

    for (int s = w; s < S_; s += 4) {
        if (lane < 16) ((float4*)qs[w])[lane] = ((const float4*)(Qb + (size_t)s * DH_))[lane];
        __syncwarp();
        float lmax = -1e30f;
        for (int t = lane; t < S_; t += 32) {
            float acc = 0.f;
#pragma unroll
            for (int d = 0; d < 64; ++d)
                acc = fmaf(qs[w][d], Kt[d * 200 + t], acc);
            acc *= 0.125f;
            probs[w][t] = acc;
            lmax = fmaxf(lmax, acc);
        }
#pragma unroll
        for (int off = 16; off > 0; off >>= 1)
            lmax = fmaxf(lmax, __shfl_xor_sync(0xffffffffu, lmax, off));
        float lsum = 0.f;
        for (int t = lane; t < S_; t += 32) {
            float p = __expf(probs[w][t] - lmax);
            probs[w][t] = p;
            lsum += p;
        }
#pragma unroll
        for (int off = 16; off > 0; off >>= 1)
            lsum += __shfl_xor_sync(0xffffffffu, lsum, off);
        const float inv = 1.f / lsum;
        __syncwarp();
        float o0 = 0.f, o1 = 0.f;
        for (int t = 0; t < S_; ++t) {
            float p = probs[w][t];
            o0 = fmaf(p, Vs[t * 64 + lane], o0);
            o1 = fmaf(p, Vs[t * 64 + lane + 32], o1);
        }
        size_t oidx = ((size_t)(b * S_ + s)) * D_ + h * DH_ + lane;
        __nv_bfloat16 hh, ll;
        split2(o0 * inv, hh, ll); Ohi[oidx] = hh; Olo[oidx] = ll;
        split2(o1 * inv, hh, ll); Ohi[oidx + 32] = hh; Olo[oidx + 32] = ll;
        __syncwarp();
    }
}

// ---------------- classifier head ----------------
__global__ void head_kernel(const float* __restrict__ cls, const float* __restrict__ W,
                            const float* __restrict__ bias, float* __restrict__ out) {
    int n = blockIdx.x * 256 + threadIdx.x;
    int b = blockIdx.y;
    if (n >= 1000) return;
    const float* xr = cls + (size_t)b * D_;
    float acc = bias[n];
    for (int k = 0; k < D_; ++k)
        acc = fmaf(xr[k], W[(size_t)k * 1000 + n], acc);
    out[(size_t)b * 1000 + n] = acc;
}

// ---------------- host launch ----------------
extern "C" void kernel_launch(void* const* d_in, const int* in_sizes, int n_in,
                              void* d_out, int out_size) {
    (void)in_sizes; (void)n_in; (void)out_size;
    const float* X       = (const float*)d_in[0];
    const float* patch_w = (const float*)d_in[1];
    const float* patch_b = (const float*)d_in[2];
    const float* cls_tok = (const float*)d_in[3];
    const float* pos_emb = (const float*)d_in[4];
    const float* ln1_g   = (const float*)d_in[5];
    const float* ln1_b   = (const float*)d_in[6];
    const float* Wq      = (const float*)d_in[7];
    const float* bq      = (const float*)d_in[8];
    const float* Wk      = (const float*)d_in[9];
    const float* bk      = (const float*)d_in[10];
    const float* Wv      = (const float*)d_in[11];
    const float* bv      = (const float*)d_in[12];
    const float* Wo      = (const float*)d_in[13];
    const float* bo      = (const float*)d_in[14];
    const float* ln2_g   = (const float*)d_in[15];
    const float* ln2_b   = (const float*)d_in[16];
    const float* Wf1     = (const float*)d_in[17];
    const float* bf1     = (const float*)d_in[18];
    const float* Wf2     = (const float*)d_in[19];
    const float* bf2     = (const float*)d_in[20];
    const float* lnf_g   = (const float*)d_in[21];
    const float* lnf_b   = (const float*)d_in[22];
    const float* head_w  = (const float*)d_in[23];
    const float* head_b  = (const float*)d_in[24];
    float* out = (float*)d_out;

    float *gx, *gq, *gk, *gv, *gcls;
    __nv_bfloat16 *whi, *wlo, *ghhi, *ghlo, *gahi, *galo, *gfhi, *gflo;
    cudaGetSymbolAddress((void**)&gx, g_x);
    cudaGetSymbolAddress((void**)&gq, g_q);
    cudaGetSymbolAddress((void**)&gk, g_k);
    cudaGetSymbolAddress((void**)&gv, g_v);
    cudaGetSymbolAddress((void**)&gcls, g_cls);
    cudaGetSymbolAddress((void**)&whi, g_w_hi);
    cudaGetSymbolAddress((void**)&wlo, g_w_lo);
    cudaGetSymbolAddress((void**)&ghhi, g_h_hi);
    cudaGetSymbolAddress((void**)&ghlo, g_h_lo);
    cudaGetSymbolAddress((void**)&gahi, g_a_hi);
    cudaGetSymbolAddress((void**)&galo, g_a_lo);
    cudaGetSymbolAddress((void**)&gfhi, g_f_hi);
    cudaGetSymbolAddress((void**)&gflo, g_f_lo);

    cudaFuncSetAttribute(mma_gemm<1>, cudaFuncAttributeMaxDynamicSharedMemorySize, SMDYN);
    cudaFuncSetAttribute(mma_gemm<2>, cudaFuncAttributeMaxDynamicSharedMemorySize, SMDYN);
    cudaFuncSetAttribute(mma_gemm<3>, cudaFuncAttributeMaxDynamicSharedMemorySize, SMDYN);
    cudaFuncSetAttribute(mma_gemm<4>, cudaFuncAttributeMaxDynamicSharedMemorySize, SMDYN);
    const int ATTN_SMEM = (64 * 200 + S_ * DH_) * 4;
    cudaFuncSetAttribute(attn_kernel, cudaFuncAttributeMaxDynamicSharedMemorySize, ATTN_SMEM);

    // ---- weight conversion (per launch; weights are inputs) ----
    dim3 tb(32, 8);
    wsplitT_kernel<<<dim3(24, 24, 12), tb>>>(Wq, whi + 0 * WSZ, wlo + 0 * WSZ, D_, D_, WSZ, LSTRIDE);
    wsplitT_kernel<<<dim3(24, 24, 12), tb>>>(Wk, whi + 1 * WSZ, wlo + 1 * WSZ, D_, D_, WSZ, LSTRIDE);
    wsplitT_kernel<<<dim3(24, 24, 12), tb>>>(Wv, whi + 2 * WSZ, wlo + 2 * WSZ, D_, D_, WSZ, LSTRIDE);
    wsplitT_kernel<<<dim3(24, 24, 12), tb>>>(Wo, whi + 3 * WSZ, wlo + 3 * WSZ, D_, D_, WSZ, LSTRIDE);
    wsplitT_kernel<<<dim3(96, 24, 12), tb>>>(Wf1, whi + 4 * WSZ, wlo + 4 * WSZ, D_, F_, (size_t)D_ * F_, LSTRIDE);
    wsplitT_kernel<<<dim3(24, 96, 12), tb>>>(Wf2, whi + 4 * WSZ + (size_t)D_ * F_,
                                             wlo + 4 * WSZ + (size_t)D_ * F_, F_, D_, (size_t)D_ * F_, LSTRIDE);
    wsplit_kernel<<<(WSZ + 255) / 256, 256>>>(patch_w, whi + PATCH_OFF, wlo + PATCH_OFF, WSZ);

    // ---- patch embed ----
    im2col_kernel<<<(NPAT * D_) / 256, 256>>>(X, gfhi, gflo);
    mma_gemm<4><<<dim3(6, 49), 256, SMDYN>>>(gfhi, gflo, whi + PATCH_OFF, wlo + PATCH_OFF,
                                             patch_b, nullptr, nullptr, nullptr,
                                             gx, nullptr, nullptr, nullptr, nullptr,
                                             NPAT, D_, D_);
    posadd_kernel<<<(NTOK * D_) / 256, 256>>>(gx, cls_tok, pos_emb);

    for (int l = 0; l < L_; ++l) {
        const size_t LOFF = (size_t)l * LSTRIDE;
        ln_bf16_kernel<<<NTOK, 256>>>(gx, ln1_g + l * D_, ln1_b + l * D_, ghhi, ghlo);
        // fused QKV: N = 2304 (WQT/WKT/WVT contiguous)
        mma_gemm<3><<<dim3(18, 50), 256, SMDYN>>>(ghhi, ghlo, whi + LOFF, wlo + LOFF,
                                                  bq + l * D_, bk + l * D_, bv + l * D_, nullptr,
                                                  gq, gk, gv, nullptr, nullptr,
                                                  NTOK, 3 * D_, D_);
        attn_kernel<<<dim3(H_, B_), 128, ATTN_SMEM>>>(gq, gk, gv, gahi, galo);
        mma_gemm<1><<<dim3(6, 50), 256, SMDYN>>>(gahi, galo, whi + LOFF + 3 * WSZ, wlo + LOFF + 3 * WSZ,
                                                 bo + l * D_, nullptr, nullptr, gx,
                                                 gx, nullptr, nullptr, nullptr, nullptr,
                                                 NTOK, D_, D_);
        ln_bf16_kernel<<<NTOK, 256>>>(gx, ln2_g + l * D_, ln2_b + l * D_, ghhi, ghlo);
        mma_gemm<2><<<dim3(24, 50), 256, SMDYN>>>(ghhi, ghlo, whi + LOFF + 4 * WSZ, wlo + LOFF + 4 * WSZ,
                                                  bf1 + l * F_, nullptr, nullptr, nullptr,
                                                  nullptr, nullptr, nullptr, gfhi, gflo,
                                                  NTOK, F_, D_);
        mma_gemm<1><<<dim3(6, 50), 256, SMDYN>>>(gfhi, gflo, whi + LOFF + 4 * WSZ + (size_t)D_ * F_,
                                                 wlo + LOFF + 4 * WSZ + (size_t)D_ * F_,
                                                 bf2 + l * D_, nullptr, nullptr, gx,
                                                 gx, nullptr, nullptr, nullptr, nullptr,
                                                 NTOK, D_, F_);
    }

    ln_f32_kernel<<<B_, 256>>>(gx, lnf_g, lnf_b, gcls, S_);
    head_kernel<<<dim3(4, B_), 256>>>(gcls, head_w, head_b, out);
}